// round 14
// baseline (speedup 1.0000x reference)
#include <cuda_runtime.h>
#include <math.h>

#define NN 100000
#define EE 1000000
#define RR 40
#define DD 64

static constexpr float PHASE_SCALE = (float)(3.1415926235897933 / ((12.0 + 2.0) / 64.0));

// ---- scratch (device globals: no runtime allocation allowed) ----
__device__ int   g_cnt[NN];
__device__ int   g_cursor[NN];
__device__ int   g_src_p[EE];
__device__ int   g_dst_p[EE];
__device__ float g_att[EE];          // RAW scores, permuted (dst-sorted) order
__device__ float g_segmax[NN];
__device__ float g_segsum[NN];       // filled during scatter128
__device__ float g_side[(size_t)NN * 128];
__device__ float g_ego1[(size_t)NN * 64];
__device__ float g_ego2[(size_t)NN * 32];
__device__ float g_ego3[(size_t)NN * 16];
__device__ float g_cr[RR * DD];
__device__ float g_sr[RR * DD];

__device__ __forceinline__ float fsqrt_approx(float x) {
    float y; asm("sqrt.approx.f32 %0, %1;" : "=f"(y) : "f"(x)); return y;
}

// packed f32x2 helpers (sm_100+)
#define FFMA_F32X2(d, a, b, c) \
    asm("fma.rn.f32x2 %0, %1, %2, %3;" : "=l"(d) : "l"(a), "l"(b), "l"(c))
#define FMUL_F32X2(d, a, b) \
    asm("mul.rn.f32x2 %0, %1, %2;" : "=l"(d) : "l"(a), "l"(b))
#define PACK2(out, v) \
    asm("mov.b64 %0, {%1, %1};" : "=l"(out) : "r"(__float_as_uint(v)))
#define PACK2V(out, lo, hi) \
    asm("mov.b64 %0, {%1, %2};" : "=l"(out) : "f"(lo), "f"(hi))
#define UNPACK2(lo, hi, in) \
    asm("mov.b64 {%0, %1}, %2;" : "=f"(lo), "=f"(hi) : "l"(in))

// ---- fused: histogram of dst + trig table build ----
__global__ void hist_trig_kernel(const int* __restrict__ edst,
                                 const float* __restrict__ rel) {
    int e = blockIdx.x * blockDim.x + threadIdx.x;
    if (e < RR * DD) {
        float ph = rel[e] * PHASE_SCALE;
        float s, c;
        sincosf(ph, &s, &c);
        g_cr[e] = c;
        g_sr[e] = s;
    }
    if (e < EE) atomicAdd(&g_cnt[edst[e]], 1);
}

__global__ void scan_kernel() {
    constexpr int CHUNK = (NN + 1023) / 1024;  // 98
    __shared__ int ssum[1024];
    int t = threadIdx.x;
    int base = t * CHUNK;
    int s = 0;
#pragma unroll 4
    for (int i = 0; i < CHUNK; i++) {
        int idx = base + i;
        if (idx < NN) s += g_cnt[idx];
    }
    ssum[t] = s;
    __syncthreads();
    for (int off = 1; off < 1024; off <<= 1) {
        int u = (t >= off) ? ssum[t - off] : 0;
        __syncthreads();
        ssum[t] += u;
        __syncthreads();
    }
    int run = ssum[t] - s;
    for (int i = 0; i < CHUNK; i++) {
        int idx = base + i;
        if (idx < NN) {
            g_cursor[idx] = run;
            run += g_cnt[idx];
        }
    }
}

// ---- attention + CSR fill + segmax, fused. Two edges per warp (ILP=2) ----
// Processes ORIGINAL edge order; lane 0 claims the dst-sorted slot via the
// cursor and emits src/dst/score there, plus atomicMax into segmax.
__global__ void __launch_bounds__(256) att_fill_kernel(const float* __restrict__ ent,
                                                       const int* __restrict__ esrc,
                                                       const int* __restrict__ edst,
                                                       const int* __restrict__ etyp) {
    int w = (blockIdx.x * blockDim.x + threadIdx.x) >> 5;
    int lane = threadIdx.x & 31;
    int e0 = w * 2;
    if (e0 >= EE) return;
    int e1 = e0 + 1;

    int s0 = esrc[e0], d0 = edst[e0], ty0 = etyp[e0];
    int s1 = esrc[e1], d1 = edst[e1], ty1 = etyp[e1];

    const float* h0 = ent + (size_t)s0 * 128;
    const float* t0 = ent + (size_t)d0 * 128;
    const float* h1 = ent + (size_t)s1 * 128;
    const float* t1 = ent + (size_t)d1 * 128;

    float2 h0re = *(const float2*)(h0 + 2 * lane);
    float2 h0im = *(const float2*)(h0 + 64 + 2 * lane);
    float2 t0re = *(const float2*)(t0 + 2 * lane);
    float2 t0im = *(const float2*)(t0 + 64 + 2 * lane);
    float2 h1re = *(const float2*)(h1 + 2 * lane);
    float2 h1im = *(const float2*)(h1 + 64 + 2 * lane);
    float2 t1re = *(const float2*)(t1 + 2 * lane);
    float2 t1im = *(const float2*)(t1 + 64 + 2 * lane);
    float2 cc0  = *(const float2*)(g_cr + ty0 * DD + 2 * lane);
    float2 sn0  = *(const float2*)(g_sr + ty0 * DD + 2 * lane);
    float2 cc1  = *(const float2*)(g_cr + ty1 * DD + 2 * lane);
    float2 sn1  = *(const float2*)(g_sr + ty1 * DD + 2 * lane);

    unsigned long long HRE0, HIM0, NHIM0, CC0, SN0, NTRE0, NTIM0;
    unsigned long long HRE1, HIM1, NHIM1, CC1, SN1, NTRE1, NTIM1;
    PACK2V(HRE0, h0re.x, h0re.y);  PACK2V(HRE1, h1re.x, h1re.y);
    PACK2V(HIM0, h0im.x, h0im.y);  PACK2V(HIM1, h1im.x, h1im.y);
    PACK2V(NHIM0, -h0im.x, -h0im.y); PACK2V(NHIM1, -h1im.x, -h1im.y);
    PACK2V(CC0, cc0.x, cc0.y);     PACK2V(CC1, cc1.x, cc1.y);
    PACK2V(SN0, sn0.x, sn0.y);     PACK2V(SN1, sn1.x, sn1.y);
    PACK2V(NTRE0, -t0re.x, -t0re.y); PACK2V(NTRE1, -t1re.x, -t1re.y);
    PACK2V(NTIM0, -t0im.x, -t0im.y); PACK2V(NTIM1, -t1im.x, -t1im.y);

    unsigned long long RS0, IS0, SQ0, RS1, IS1, SQ1;
    FFMA_F32X2(RS0, HRE0, CC0, NTRE0);  FFMA_F32X2(RS1, HRE1, CC1, NTRE1);
    FFMA_F32X2(RS0, NHIM0, SN0, RS0);   FFMA_F32X2(RS1, NHIM1, SN1, RS1);
    FFMA_F32X2(IS0, HRE0, SN0, NTIM0);  FFMA_F32X2(IS1, HRE1, SN1, NTIM1);
    FFMA_F32X2(IS0, HIM0, CC0, IS0);    FFMA_F32X2(IS1, HIM1, CC1, IS1);
    FMUL_F32X2(SQ0, RS0, RS0);          FMUL_F32X2(SQ1, RS1, RS1);
    FFMA_F32X2(SQ0, IS0, IS0, SQ0);     FFMA_F32X2(SQ1, IS1, IS1, SQ1);

    float a0, b0, a1, b1;
    UNPACK2(a0, b0, SQ0);
    UNPACK2(a1, b1, SQ1);
    float term0 = fsqrt_approx(a0) + fsqrt_approx(b0);
    float term1 = fsqrt_approx(a1) + fsqrt_approx(b1);

    term0 += __shfl_xor_sync(0xffffffffu, term0, 16);
    term1 += __shfl_xor_sync(0xffffffffu, term1, 16);
    term0 += __shfl_xor_sync(0xffffffffu, term0, 8);
    term1 += __shfl_xor_sync(0xffffffffu, term1, 8);
    term0 += __shfl_xor_sync(0xffffffffu, term0, 4);
    term1 += __shfl_xor_sync(0xffffffffu, term1, 4);
    term0 += __shfl_xor_sync(0xffffffffu, term0, 2);
    term1 += __shfl_xor_sync(0xffffffffu, term1, 2);
    term0 += __shfl_xor_sync(0xffffffffu, term0, 1);
    term1 += __shfl_xor_sync(0xffffffffu, term1, 1);

    if (lane == 0) {
        // scores >= 0 -> int-compare atomicMax on float bits exact; init 0 ok
        atomicMax((int*)&g_segmax[d0], __float_as_int(term0));
        atomicMax((int*)&g_segmax[d1], __float_as_int(term1));
        int p0 = atomicAdd(&g_cursor[d0], 1);
        int p1 = atomicAdd(&g_cursor[d1], 1);
        g_src_p[p0] = s0; g_dst_p[p0] = d0; g_att[p0] = term0;
        g_src_p[p1] = s1; g_dst_p[p1] = d1; g_att[p1] = term1;
    }
}

// ---- run-aggregated scatter over dst-sorted edges, exp on the fly ----
// side_unnorm[d] = sum exp(att-segmax[d]) * ego[src]; normalization by
// segsum happens in layer staging (division distributes over the sum).
// SEGSUM: scatter128 (first) also accumulates g_segsum (c==0, per run).
template <int DIN, bool SEGSUM>
__global__ void scatter_agg_kernel(const float* __restrict__ ego) {
    constexpr int CH = DIN / 4;
    int t = blockIdx.x * blockDim.x + threadIdx.x;
    int c = t % CH;
    int g = t / CH;
    int ebase = g * 8;        // EE divisible by 8
    if (ebase >= EE) return;

    int dd[8], ss[8];
    float at[8], mx[8];
    float4 v[8];
#pragma unroll
    for (int i = 0; i < 8; i++) dd[i] = g_dst_p[ebase + i];
#pragma unroll
    for (int i = 0; i < 8; i++) ss[i] = g_src_p[ebase + i];
#pragma unroll
    for (int i = 0; i < 8; i++) at[i] = g_att[ebase + i];
#pragma unroll
    for (int i = 0; i < 8; i++) mx[i] = g_segmax[dd[i]];
#pragma unroll
    for (int i = 0; i < 8; i++)
        v[i] = *(const float4*)(ego + (size_t)ss[i] * DIN + c * 4);

    int cur = dd[0];
    float4 acc = {0.f, 0.f, 0.f, 0.f};
    float srun = 0.f;
#pragma unroll
    for (int i = 0; i < 8; i++) {
        if (dd[i] != cur) {
            float* o = g_side + (size_t)cur * DIN + c * 4;
            asm volatile("red.global.add.v4.f32 [%0], {%1, %2, %3, %4};"
                         :: "l"(o), "f"(acc.x), "f"(acc.y), "f"(acc.z), "f"(acc.w)
                         : "memory");
            if (SEGSUM && c == 0) atomicAdd(&g_segsum[cur], srun);
            acc.x = acc.y = acc.z = acc.w = 0.f;
            srun = 0.f;
            cur = dd[i];
        }
        float a = __expf(at[i] - mx[i]);
        srun += a;
        acc.x += a * v[i].x; acc.y += a * v[i].y;
        acc.z += a * v[i].z; acc.w += a * v[i].w;
    }
    float* o = g_side + (size_t)cur * DIN + c * 4;
    asm volatile("red.global.add.v4.f32 [%0], {%1, %2, %3, %4};"
                 :: "l"(o), "f"(acc.x), "f"(acc.y), "f"(acc.z), "f"(acc.w)
                 : "memory");
    if (SEGSUM && c == 0) atomicAdd(&g_segsum[cur], srun);
}

// ---- per-node dense layer (R8 structure); staging divides side by segsum ----
template <int DIN, int DOUT, int Y>
__global__ void layer_kernel(const float* __restrict__ ego,
                             const float* __restrict__ W1, const float* __restrict__ b1,
                             const float* __restrict__ W2, const float* __restrict__ b2,
                             float* __restrict__ ego_out,
                             float* __restrict__ out, int out_col) {
    constexpr int XT = DOUT / 8;
    constexpr int NPT = 4;
    constexpr int YW = Y / NPT;
    extern __shared__ float sh[];
    float* w1s = sh;                       // DIN*DOUT
    float* w2s = w1s + DIN * DOUT;         // DIN*DOUT
    float* sa  = w2s + DIN * DOUT;         // Y*(DIN+1)
    float* smm = sa + Y * (DIN + 1);       // Y*(DIN+1)
    float* nrm = smm + Y * (DIN + 1);      // Y

    int tid = threadIdx.y * XT + threadIdx.x;
    constexpr int NT = XT * YW;            // 256 threads

    for (int i = tid; i < DIN * DOUT; i += NT) { w1s[i] = W1[i]; w2s[i] = W2[i]; }

    int nbase = blockIdx.x * Y;
    for (int i = tid; i < Y * DIN; i += NT) {
        int yl = i / DIN, k = i - yl * DIN;
        int n = nbase + yl;
        float ev = 0.f, sv = 0.f;
        if (n < NN) {
            ev = ego[(size_t)n * DIN + k];
            float ssn = g_segsum[n];
            float svr = g_side[(size_t)n * DIN + k];
            sv = (ssn > 0.f) ? __fdividef(svr, ssn) : 0.f;  // zero-degree guard
        }
        sa[yl * (DIN + 1) + k]  = ev + sv;
        smm[yl * (DIN + 1) + k] = ev * sv;
    }
    for (int i = tid; i < Y; i += NT) nrm[i] = 0.f;
    __syncthreads();

    int x = threadIdx.x, yw = threadIdx.y;
    unsigned long long acc1[NPT][4], acc2[NPT][4];
    {
        const ulonglong2* b1p = (const ulonglong2*)(b1 + x * 8);
        const ulonglong2* b2p = (const ulonglong2*)(b2 + x * 8);
        ulonglong2 t1a = b1p[0], t1b = b1p[1];
        ulonglong2 t2a = b2p[0], t2b = b2p[1];
#pragma unroll
        for (int n = 0; n < NPT; n++) {
            acc1[n][0] = t1a.x; acc1[n][1] = t1a.y; acc1[n][2] = t1b.x; acc1[n][3] = t1b.y;
            acc2[n][0] = t2a.x; acc2[n][1] = t2a.y; acc2[n][2] = t2b.x; acc2[n][3] = t2b.y;
        }
    }

    const float* ap = sa + (yw * NPT) * (DIN + 1);
    const float* mp = smm + (yw * NPT) * (DIN + 1);
#pragma unroll 2
    for (int k = 0; k < DIN; k++) {
        const ulonglong2* w1p = (const ulonglong2*)(w1s + k * DOUT + x * 8);
        const ulonglong2* w2p = (const ulonglong2*)(w2s + k * DOUT + x * 8);
        ulonglong2 wa = w1p[0], wb = w1p[1];
        ulonglong2 wc = w2p[0], wd = w2p[1];
#pragma unroll
        for (int n = 0; n < NPT; n++) {
            float a = ap[n * (DIN + 1) + k];
            float m = mp[n * (DIN + 1) + k];
            unsigned long long aa, mm;
            PACK2(aa, a);
            PACK2(mm, m);
            FFMA_F32X2(acc1[n][0], aa, wa.x, acc1[n][0]);
            FFMA_F32X2(acc1[n][1], aa, wa.y, acc1[n][1]);
            FFMA_F32X2(acc1[n][2], aa, wb.x, acc1[n][2]);
            FFMA_F32X2(acc1[n][3], aa, wb.y, acc1[n][3]);
            FFMA_F32X2(acc2[n][0], mm, wc.x, acc2[n][0]);
            FFMA_F32X2(acc2[n][1], mm, wc.y, acc2[n][1]);
            FFMA_F32X2(acc2[n][2], mm, wd.x, acc2[n][2]);
            FFMA_F32X2(acc2[n][3], mm, wd.y, acc2[n][3]);
        }
    }

    float vloc[NPT][8];
#pragma unroll
    for (int n = 0; n < NPT; n++) {
        float ssq = 0.f;
#pragma unroll
        for (int j = 0; j < 4; j++) {
            float a1lo, a1hi, a2lo, a2hi;
            UNPACK2(a1lo, a1hi, acc1[n][j]);
            UNPACK2(a2lo, a2hi, acc2[n][j]);
            float o1 = a1lo > 0.f ? a1lo : 0.01f * a1lo;
            float o2 = a2lo > 0.f ? a2lo : 0.01f * a2lo;
            float vv = o1 + o2;
            vloc[n][2 * j] = vv;
            ssq += vv * vv;
            o1 = a1hi > 0.f ? a1hi : 0.01f * a1hi;
            o2 = a2hi > 0.f ? a2hi : 0.01f * a2hi;
            vv = o1 + o2;
            vloc[n][2 * j + 1] = vv;
            ssq += vv * vv;
        }
        atomicAdd(&nrm[yw * NPT + n], ssq);
    }
    __syncthreads();

#pragma unroll
    for (int n = 0; n < NPT; n++) {
        int node = nbase + yw * NPT + n;
        if (node < NN) {
            float inv = 1.f / fmaxf(sqrtf(nrm[yw * NPT + n]), 1e-12f);
#pragma unroll
            for (int j = 0; j < 8; j++) {
                int col = x * 8 + j;
                ego_out[(size_t)node * DOUT + col] = vloc[n][j];
                out[(size_t)node * 240 + out_col + col] = vloc[n][j] * inv;
            }
        }
    }
}

// ---- copy raw ent_embed into output columns [0,128) ----
__global__ void copy_kernel(const float* __restrict__ ent, float* __restrict__ out) {
    int i = blockIdx.x * blockDim.x + threadIdx.x;
    if (i < NN * 128) {
        int n = i >> 7, k = i & 127;
        out[(size_t)n * 240 + k] = ent[i];
    }
}

extern "C" void kernel_launch(void* const* d_in, const int* in_sizes, int n_in,
                              void* d_out, int out_size) {
    const float* ent  = (const float*)d_in[0];
    const float* rel  = (const float*)d_in[1];
    const float* W1_0 = (const float*)d_in[2];
    const float* b1_0 = (const float*)d_in[3];
    const float* W2_0 = (const float*)d_in[4];
    const float* b2_0 = (const float*)d_in[5];
    const float* W1_1 = (const float*)d_in[6];
    const float* b1_1 = (const float*)d_in[7];
    const float* W2_1 = (const float*)d_in[8];
    const float* b2_1 = (const float*)d_in[9];
    const float* W1_2 = (const float*)d_in[10];
    const float* b1_2 = (const float*)d_in[11];
    const float* W2_2 = (const float*)d_in[12];
    const float* b2_2 = (const float*)d_in[13];
    const int* esrc = (const int*)d_in[14];
    const int* edst = (const int*)d_in[15];
    const int* etyp = (const int*)d_in[16];
    float* out = (float*)d_out;

    void *p_cnt, *p_max, *p_sum, *p_side, *p_ego1, *p_ego2, *p_ego3;
    cudaGetSymbolAddress(&p_cnt, g_cnt);
    cudaGetSymbolAddress(&p_max, g_segmax);
    cudaGetSymbolAddress(&p_sum, g_segsum);
    cudaGetSymbolAddress(&p_side, g_side);
    cudaGetSymbolAddress(&p_ego1, g_ego1);
    cudaGetSymbolAddress(&p_ego2, g_ego2);
    cudaGetSymbolAddress(&p_ego3, g_ego3);

    cudaFuncSetAttribute(layer_kernel<128, 64, 128>,
                         cudaFuncAttributeMaxDynamicSharedMemorySize, 198144);
    cudaFuncSetAttribute(layer_kernel<64, 32, 256>,
                         cudaFuncAttributeMaxDynamicSharedMemorySize, 150528);
    cudaFuncSetAttribute(layer_kernel<32, 16, 512>,
                         cudaFuncAttributeMaxDynamicSharedMemorySize, 141312);

    // Chain shortened so scatter128 is the 4th __global__ -> ncu capture slot.
    cudaMemsetAsync(p_cnt, 0, NN * sizeof(int));
    cudaMemsetAsync(p_max, 0, NN * sizeof(float));
    cudaMemsetAsync(p_sum, 0, NN * sizeof(float));
    cudaMemsetAsync(p_side, 0, (size_t)NN * 128 * sizeof(float));
    hist_trig_kernel<<<(EE + 255) / 256, 256>>>(edst, rel);          // 1
    scan_kernel<<<1, 1024>>>();                                      // 2
    att_fill_kernel<<<EE / 16, 256>>>(ent, esrc, edst, etyp);        // 3

    // layer 0 (din=128 -> dout=64)
    scatter_agg_kernel<128, true><<<(EE / 8 * 32 + 255) / 256, 256>>>(ent);  // 4 <- profiled
    layer_kernel<128, 64, 128><<<(NN + 127) / 128, dim3(8, 32), 198144>>>(
        ent, W1_0, b1_0, W2_0, b2_0, (float*)p_ego1, out, 128);

    // layer 1 (64 -> 32)
    cudaMemsetAsync(p_side, 0, (size_t)NN * 64 * sizeof(float));
    scatter_agg_kernel<64, false><<<(EE / 8 * 16 + 255) / 256, 256>>>((const float*)p_ego1);
    layer_kernel<64, 32, 256><<<(NN + 255) / 256, dim3(4, 64), 150528>>>(
        (const float*)p_ego1, W1_1, b1_1, W2_1, b2_1, (float*)p_ego2, out, 192);

    // layer 2 (32 -> 16)
    cudaMemsetAsync(p_side, 0, (size_t)NN * 32 * sizeof(float));
    scatter_agg_kernel<32, false><<<(EE / 8 * 8 + 255) / 256, 256>>>((const float*)p_ego2);
    layer_kernel<32, 16, 512><<<(NN + 511) / 512, dim3(2, 128), 141312>>>(
        (const float*)p_ego2, W1_2, b1_2, W2_2, b2_2, (float*)p_ego3, out, 224);

    copy_kernel<<<(NN * 128 + 255) / 256, 256>>>(ent, out);
}

// round 15
// speedup vs baseline: 1.8053x; 1.8053x over previous
#include <cuda_runtime.h>
#include <math.h>

#define NN 100000
#define EE 1000000
#define RR 40
#define DD 64

static constexpr float PHASE_SCALE = (float)(3.1415926235897933 / ((12.0 + 2.0) / 64.0));

// ---- scratch (device globals: no runtime allocation allowed) ----
__device__ int   g_cnt[NN];
__device__ int   g_cursor[NN];
__device__ int   g_src_p[EE];
__device__ int   g_dst_p[EE];
__device__ int   g_typ_p[EE];
__device__ float g_att[EE];
__device__ float g_segmax[NN];
__device__ float g_segsum[NN];
__device__ float g_side[(size_t)NN * 128];
__device__ float g_ego1[(size_t)NN * 64];
__device__ float g_ego2[(size_t)NN * 32];
__device__ float g_ego3[(size_t)NN * 16];
__device__ float g_cr[RR * DD];
__device__ float g_sr[RR * DD];

__device__ __forceinline__ float fsqrt_approx(float x) {
    float y; asm("sqrt.approx.f32 %0, %1;" : "=f"(y) : "f"(x)); return y;
}

// packed f32x2 helpers (sm_100+)
#define FFMA_F32X2(d, a, b, c) \
    asm("fma.rn.f32x2 %0, %1, %2, %3;" : "=l"(d) : "l"(a), "l"(b), "l"(c))
#define FMUL_F32X2(d, a, b) \
    asm("mul.rn.f32x2 %0, %1, %2;" : "=l"(d) : "l"(a), "l"(b))
#define PACK2(out, v) \
    asm("mov.b64 %0, {%1, %1};" : "=l"(out) : "r"(__float_as_uint(v)))
#define PACK2V(out, lo, hi) \
    asm("mov.b64 %0, {%1, %2};" : "=l"(out) : "f"(lo), "f"(hi))
#define UNPACK2(lo, hi, in) \
    asm("mov.b64 {%0, %1}, %2;" : "=f"(lo), "=f"(hi) : "l"(in))

// ---- fused: histogram of dst + trig table build ----
__global__ void hist_trig_kernel(const int* __restrict__ edst,
                                 const float* __restrict__ rel) {
    int e = blockIdx.x * blockDim.x + threadIdx.x;
    if (e < RR * DD) {
        float ph = rel[e] * PHASE_SCALE;
        float s, c;
        sincosf(ph, &s, &c);
        g_cr[e] = c;
        g_sr[e] = s;
    }
    if (e < EE) atomicAdd(&g_cnt[edst[e]], 1);
}

__global__ void scan_kernel() {
    constexpr int CHUNK = (NN + 1023) / 1024;  // 98
    __shared__ int ssum[1024];
    int t = threadIdx.x;
    int base = t * CHUNK;
    int s = 0;
#pragma unroll 4
    for (int i = 0; i < CHUNK; i++) {
        int idx = base + i;
        if (idx < NN) s += g_cnt[idx];
    }
    ssum[t] = s;
    __syncthreads();
    for (int off = 1; off < 1024; off <<= 1) {
        int u = (t >= off) ? ssum[t - off] : 0;
        __syncthreads();
        ssum[t] += u;
        __syncthreads();
    }
    int run = ssum[t] - s;
    for (int i = 0; i < CHUNK; i++) {
        int idx = base + i;
        if (idx < NN) {
            g_cursor[idx] = run;
            run += g_cnt[idx];
        }
    }
}

__global__ void fill_kernel(const int* __restrict__ esrc,
                            const int* __restrict__ edst,
                            const int* __restrict__ etyp) {
    int e = blockIdx.x * blockDim.x + threadIdx.x;
    if (e < EE) {
        int d = edst[e];
        int pos = atomicAdd(&g_cursor[d], 1);
        g_src_p[pos] = esrc[e];
        g_dst_p[pos] = d;
        g_typ_p[pos] = etyp[e];
    }
}

// ---- raw attention: TWO edges per warp (ILP=2), unchanged from R12 ----
__global__ void __launch_bounds__(256) att_kernel(const float* __restrict__ ent) {
    int w = (blockIdx.x * blockDim.x + threadIdx.x) >> 5;
    int lane = threadIdx.x & 31;
    int e0 = w * 2;
    if (e0 >= EE) return;
    int e1 = e0 + 1;

    int s0 = g_src_p[e0], d0 = g_dst_p[e0], ty0 = g_typ_p[e0];
    int s1 = g_src_p[e1], d1 = g_dst_p[e1], ty1 = g_typ_p[e1];

    const float* h0 = ent + (size_t)s0 * 128;
    const float* t0 = ent + (size_t)d0 * 128;
    const float* h1 = ent + (size_t)s1 * 128;
    const float* t1 = ent + (size_t)d1 * 128;

    float2 h0re = *(const float2*)(h0 + 2 * lane);
    float2 h0im = *(const float2*)(h0 + 64 + 2 * lane);
    float2 t0re = *(const float2*)(t0 + 2 * lane);
    float2 t0im = *(const float2*)(t0 + 64 + 2 * lane);
    float2 h1re = *(const float2*)(h1 + 2 * lane);
    float2 h1im = *(const float2*)(h1 + 64 + 2 * lane);
    float2 t1re = *(const float2*)(t1 + 2 * lane);
    float2 t1im = *(const float2*)(t1 + 64 + 2 * lane);
    float2 cc0  = *(const float2*)(g_cr + ty0 * DD + 2 * lane);
    float2 sn0  = *(const float2*)(g_sr + ty0 * DD + 2 * lane);
    float2 cc1  = *(const float2*)(g_cr + ty1 * DD + 2 * lane);
    float2 sn1  = *(const float2*)(g_sr + ty1 * DD + 2 * lane);

    unsigned long long HRE0, HIM0, NHIM0, CC0, SN0, NTRE0, NTIM0;
    unsigned long long HRE1, HIM1, NHIM1, CC1, SN1, NTRE1, NTIM1;
    PACK2V(HRE0, h0re.x, h0re.y);  PACK2V(HRE1, h1re.x, h1re.y);
    PACK2V(HIM0, h0im.x, h0im.y);  PACK2V(HIM1, h1im.x, h1im.y);
    PACK2V(NHIM0, -h0im.x, -h0im.y); PACK2V(NHIM1, -h1im.x, -h1im.y);
    PACK2V(CC0, cc0.x, cc0.y);     PACK2V(CC1, cc1.x, cc1.y);
    PACK2V(SN0, sn0.x, sn0.y);     PACK2V(SN1, sn1.x, sn1.y);
    PACK2V(NTRE0, -t0re.x, -t0re.y); PACK2V(NTRE1, -t1re.x, -t1re.y);
    PACK2V(NTIM0, -t0im.x, -t0im.y); PACK2V(NTIM1, -t1im.x, -t1im.y);

    unsigned long long RS0, IS0, SQ0, RS1, IS1, SQ1;
    FFMA_F32X2(RS0, HRE0, CC0, NTRE0);  FFMA_F32X2(RS1, HRE1, CC1, NTRE1);
    FFMA_F32X2(RS0, NHIM0, SN0, RS0);   FFMA_F32X2(RS1, NHIM1, SN1, RS1);
    FFMA_F32X2(IS0, HRE0, SN0, NTIM0);  FFMA_F32X2(IS1, HRE1, SN1, NTIM1);
    FFMA_F32X2(IS0, HIM0, CC0, IS0);    FFMA_F32X2(IS1, HIM1, CC1, IS1);
    FMUL_F32X2(SQ0, RS0, RS0);          FMUL_F32X2(SQ1, RS1, RS1);
    FFMA_F32X2(SQ0, IS0, IS0, SQ0);     FFMA_F32X2(SQ1, IS1, IS1, SQ1);

    float a0, b0, a1, b1;
    UNPACK2(a0, b0, SQ0);
    UNPACK2(a1, b1, SQ1);
    float term0 = fsqrt_approx(a0) + fsqrt_approx(b0);
    float term1 = fsqrt_approx(a1) + fsqrt_approx(b1);

    term0 += __shfl_xor_sync(0xffffffffu, term0, 16);
    term1 += __shfl_xor_sync(0xffffffffu, term1, 16);
    term0 += __shfl_xor_sync(0xffffffffu, term0, 8);
    term1 += __shfl_xor_sync(0xffffffffu, term1, 8);
    term0 += __shfl_xor_sync(0xffffffffu, term0, 4);
    term1 += __shfl_xor_sync(0xffffffffu, term1, 4);
    term0 += __shfl_xor_sync(0xffffffffu, term0, 2);
    term1 += __shfl_xor_sync(0xffffffffu, term1, 2);
    term0 += __shfl_xor_sync(0xffffffffu, term0, 1);
    term1 += __shfl_xor_sync(0xffffffffu, term1, 1);
    if (lane == 0) {
        float2 r = {term0, term1};
        *(float2*)(g_att + e0) = r;
    }
}

// ---- edge softmax (max, exp+sum); normalization folded into scatter ----
__global__ void segmax_kernel() {
    int e = blockIdx.x * blockDim.x + threadIdx.x;
    if (e < EE)
        atomicMax((int*)&g_segmax[g_dst_p[e]], __float_as_int(g_att[e]));
}

__global__ void expsum_kernel() {
    int e = blockIdx.x * blockDim.x + threadIdx.x;
    if (e < EE) {
        int d = g_dst_p[e];
        float v = __expf(g_att[e] - g_segmax[d]);
        g_att[e] = v;
        atomicAdd(&g_segsum[d], v);
    }
}

// ---- run-aggregated scatter over dst-sorted edges (R13 hoisted form) ----
template <int DIN>
__global__ void scatter_agg_kernel(const float* __restrict__ ego) {
    constexpr int CH = DIN / 4;
    int t = blockIdx.x * blockDim.x + threadIdx.x;
    int c = t % CH;
    int g = t / CH;
    int ebase = g * 8;        // EE divisible by 8
    if (ebase >= EE) return;

    int dd[8], ss[8];
    float at[8], sm[8];
    float4 v[8];
#pragma unroll
    for (int i = 0; i < 8; i++) dd[i] = g_dst_p[ebase + i];
#pragma unroll
    for (int i = 0; i < 8; i++) ss[i] = g_src_p[ebase + i];
#pragma unroll
    for (int i = 0; i < 8; i++) at[i] = g_att[ebase + i];
#pragma unroll
    for (int i = 0; i < 8; i++) sm[i] = g_segsum[dd[i]];
#pragma unroll
    for (int i = 0; i < 8; i++)
        v[i] = *(const float4*)(ego + (size_t)ss[i] * DIN + c * 4);

    int cur = dd[0];
    float4 acc = {0.f, 0.f, 0.f, 0.f};
#pragma unroll
    for (int i = 0; i < 8; i++) {
        if (dd[i] != cur) {
            float* o = g_side + (size_t)cur * DIN + c * 4;
            asm volatile("red.global.add.v4.f32 [%0], {%1, %2, %3, %4};"
                         :: "l"(o), "f"(acc.x), "f"(acc.y), "f"(acc.z), "f"(acc.w)
                         : "memory");
            acc.x = acc.y = acc.z = acc.w = 0.f;
            cur = dd[i];
        }
        float a = __fdividef(at[i], sm[i]);
        acc.x += a * v[i].x; acc.y += a * v[i].y;
        acc.z += a * v[i].z; acc.w += a * v[i].w;
    }
    float* o = g_side + (size_t)cur * DIN + c * 4;
    asm volatile("red.global.add.v4.f32 [%0], {%1, %2, %3, %4};"
                 :: "l"(o), "f"(acc.x), "f"(acc.y), "f"(acc.z), "f"(acc.w)
                 : "memory");
}

// ---- per-node dense layer: R8 smem layout, but 512 threads (NPT=2) ----
// Same Y (same smem, 1 CTA/SM) with DOUBLE the warps: 16 warps/SM = 4/SMSP
// covering the LDS(29)->FFMA2 latency chains that bind at 2/SMSP.
template <int DIN, int DOUT, int Y>
__global__ void __launch_bounds__(512) layer_kernel(
                             const float* __restrict__ ego,
                             const float* __restrict__ W1, const float* __restrict__ b1,
                             const float* __restrict__ W2, const float* __restrict__ b2,
                             float* __restrict__ ego_out,
                             float* __restrict__ out, int out_col) {
    constexpr int XT = DOUT / 8;
    constexpr int NPT = 2;
    constexpr int YW = Y / NPT;
    extern __shared__ float sh[];
    float* w1s = sh;                       // DIN*DOUT
    float* w2s = w1s + DIN * DOUT;         // DIN*DOUT
    float* sa  = w2s + DIN * DOUT;         // Y*(DIN+1)
    float* smm = sa + Y * (DIN + 1);       // Y*(DIN+1)
    float* nrm = smm + Y * (DIN + 1);      // Y

    int tid = threadIdx.y * XT + threadIdx.x;
    constexpr int NT = XT * YW;            // 512 threads

    for (int i = tid; i < DIN * DOUT; i += NT) { w1s[i] = W1[i]; w2s[i] = W2[i]; }

    int nbase = blockIdx.x * Y;
    for (int i = tid; i < Y * DIN; i += NT) {
        int yl = i / DIN, k = i - yl * DIN;
        int n = nbase + yl;
        float ev = 0.f, sv = 0.f;
        if (n < NN) {
            ev = ego[(size_t)n * DIN + k];
            sv = g_side[(size_t)n * DIN + k];
        }
        sa[yl * (DIN + 1) + k]  = ev + sv;
        smm[yl * (DIN + 1) + k] = ev * sv;
    }
    for (int i = tid; i < Y; i += NT) nrm[i] = 0.f;
    __syncthreads();

    int x = threadIdx.x, yw = threadIdx.y;
    unsigned long long acc1[NPT][4], acc2[NPT][4];
    {
        const ulonglong2* b1p = (const ulonglong2*)(b1 + x * 8);
        const ulonglong2* b2p = (const ulonglong2*)(b2 + x * 8);
        ulonglong2 t1a = b1p[0], t1b = b1p[1];
        ulonglong2 t2a = b2p[0], t2b = b2p[1];
#pragma unroll
        for (int n = 0; n < NPT; n++) {
            acc1[n][0] = t1a.x; acc1[n][1] = t1a.y; acc1[n][2] = t1b.x; acc1[n][3] = t1b.y;
            acc2[n][0] = t2a.x; acc2[n][1] = t2a.y; acc2[n][2] = t2b.x; acc2[n][3] = t2b.y;
        }
    }

    const float* ap = sa + (yw * NPT) * (DIN + 1);
    const float* mp = smm + (yw * NPT) * (DIN + 1);
#pragma unroll 2
    for (int k = 0; k < DIN; k++) {
        const ulonglong2* w1p = (const ulonglong2*)(w1s + k * DOUT + x * 8);
        const ulonglong2* w2p = (const ulonglong2*)(w2s + k * DOUT + x * 8);
        ulonglong2 wa = w1p[0], wb = w1p[1];
        ulonglong2 wc = w2p[0], wd = w2p[1];
#pragma unroll
        for (int n = 0; n < NPT; n++) {
            float a = ap[n * (DIN + 1) + k];
            float m = mp[n * (DIN + 1) + k];
            unsigned long long aa, mm;
            PACK2(aa, a);
            PACK2(mm, m);
            FFMA_F32X2(acc1[n][0], aa, wa.x, acc1[n][0]);
            FFMA_F32X2(acc1[n][1], aa, wa.y, acc1[n][1]);
            FFMA_F32X2(acc1[n][2], aa, wb.x, acc1[n][2]);
            FFMA_F32X2(acc1[n][3], aa, wb.y, acc1[n][3]);
            FFMA_F32X2(acc2[n][0], mm, wc.x, acc2[n][0]);
            FFMA_F32X2(acc2[n][1], mm, wc.y, acc2[n][1]);
            FFMA_F32X2(acc2[n][2], mm, wd.x, acc2[n][2]);
            FFMA_F32X2(acc2[n][3], mm, wd.y, acc2[n][3]);
        }
    }

    float vloc[NPT][8];
#pragma unroll
    for (int n = 0; n < NPT; n++) {
        float ss = 0.f;
#pragma unroll
        for (int j = 0; j < 4; j++) {
            float a1lo, a1hi, a2lo, a2hi;
            UNPACK2(a1lo, a1hi, acc1[n][j]);
            UNPACK2(a2lo, a2hi, acc2[n][j]);
            float o1 = a1lo > 0.f ? a1lo : 0.01f * a1lo;
            float o2 = a2lo > 0.f ? a2lo : 0.01f * a2lo;
            float v = o1 + o2;
            vloc[n][2 * j] = v;
            ss += v * v;
            o1 = a1hi > 0.f ? a1hi : 0.01f * a1hi;
            o2 = a2hi > 0.f ? a2hi : 0.01f * a2hi;
            v = o1 + o2;
            vloc[n][2 * j + 1] = v;
            ss += v * v;
        }
        atomicAdd(&nrm[yw * NPT + n], ss);
    }
    __syncthreads();

#pragma unroll
    for (int n = 0; n < NPT; n++) {
        int node = nbase + yw * NPT + n;
        if (node < NN) {
            float inv = 1.f / fmaxf(sqrtf(nrm[yw * NPT + n]), 1e-12f);
#pragma unroll
            for (int j = 0; j < 8; j++) {
                int col = x * 8 + j;
                ego_out[(size_t)node * DOUT + col] = vloc[n][j];
                out[(size_t)node * 240 + out_col + col] = vloc[n][j] * inv;
            }
        }
    }
}

// ---- copy raw ent_embed into output columns [0,128) ----
__global__ void copy_kernel(const float* __restrict__ ent, float* __restrict__ out) {
    int i = blockIdx.x * blockDim.x + threadIdx.x;
    if (i < NN * 128) {
        int n = i >> 7, k = i & 127;
        out[(size_t)n * 240 + k] = ent[i];
    }
}

extern "C" void kernel_launch(void* const* d_in, const int* in_sizes, int n_in,
                              void* d_out, int out_size) {
    const float* ent  = (const float*)d_in[0];
    const float* rel  = (const float*)d_in[1];
    const float* W1_0 = (const float*)d_in[2];
    const float* b1_0 = (const float*)d_in[3];
    const float* W2_0 = (const float*)d_in[4];
    const float* b2_0 = (const float*)d_in[5];
    const float* W1_1 = (const float*)d_in[6];
    const float* b1_1 = (const float*)d_in[7];
    const float* W2_1 = (const float*)d_in[8];
    const float* b2_1 = (const float*)d_in[9];
    const float* W1_2 = (const float*)d_in[10];
    const float* b1_2 = (const float*)d_in[11];
    const float* W2_2 = (const float*)d_in[12];
    const float* b2_2 = (const float*)d_in[13];
    const int* esrc = (const int*)d_in[14];
    const int* edst = (const int*)d_in[15];
    const int* etyp = (const int*)d_in[16];
    float* out = (float*)d_out;

    void *p_cnt, *p_max, *p_sum, *p_side, *p_ego1, *p_ego2, *p_ego3;
    cudaGetSymbolAddress(&p_cnt, g_cnt);
    cudaGetSymbolAddress(&p_max, g_segmax);
    cudaGetSymbolAddress(&p_sum, g_segsum);
    cudaGetSymbolAddress(&p_side, g_side);
    cudaGetSymbolAddress(&p_ego1, g_ego1);
    cudaGetSymbolAddress(&p_ego2, g_ego2);
    cudaGetSymbolAddress(&p_ego3, g_ego3);

    cudaFuncSetAttribute(layer_kernel<128, 64, 128>,
                         cudaFuncAttributeMaxDynamicSharedMemorySize, 198144);
    cudaFuncSetAttribute(layer_kernel<64, 32, 256>,
                         cudaFuncAttributeMaxDynamicSharedMemorySize, 150528);
    cudaFuncSetAttribute(layer_kernel<32, 16, 512>,
                         cudaFuncAttributeMaxDynamicSharedMemorySize, 141312);

    // Launch order: att_kernel is the 4th user kernel -> ncu capture slot.
    cudaMemsetAsync(p_cnt, 0, NN * sizeof(int));
    hist_trig_kernel<<<(EE + 255) / 256, 256>>>(edst, rel);      // 1
    scan_kernel<<<1, 1024>>>();                                  // 2
    fill_kernel<<<(EE + 255) / 256, 256>>>(esrc, edst, etyp);    // 3
    att_kernel<<<EE / 16, 256>>>(ent);                           // 4 <- profiled

    cudaMemsetAsync(p_max, 0, NN * sizeof(float));
    cudaMemsetAsync(p_sum, 0, NN * sizeof(float));
    segmax_kernel<<<(EE + 255) / 256, 256>>>();
    expsum_kernel<<<(EE + 255) / 256, 256>>>();
    copy_kernel<<<(NN * 128 + 255) / 256, 256>>>(ent, out);

    // layer 0 (din=128 -> dout=64)
    cudaMemsetAsync(p_side, 0, (size_t)NN * 128 * sizeof(float));
    scatter_agg_kernel<128><<<(EE / 8 * 32 + 255) / 256, 256>>>(ent);
    layer_kernel<128, 64, 128><<<(NN + 127) / 128, dim3(8, 64), 198144>>>(
        ent, W1_0, b1_0, W2_0, b2_0, (float*)p_ego1, out, 128);

    // layer 1 (64 -> 32)
    cudaMemsetAsync(p_side, 0, (size_t)NN * 64 * sizeof(float));
    scatter_agg_kernel<64><<<(EE / 8 * 16 + 255) / 256, 256>>>((const float*)p_ego1);
    layer_kernel<64, 32, 256><<<(NN + 255) / 256, dim3(4, 128), 150528>>>(
        (const float*)p_ego1, W1_1, b1_1, W2_1, b2_1, (float*)p_ego2, out, 192);

    // layer 2 (32 -> 16)
    cudaMemsetAsync(p_side, 0, (size_t)NN * 32 * sizeof(float));
    scatter_agg_kernel<32><<<(EE / 8 * 8 + 255) / 256, 256>>>((const float*)p_ego2);
    layer_kernel<32, 16, 512><<<(NN + 511) / 512, dim3(2, 256), 141312>>>(
        (const float*)p_ego2, W1_2, b1_2, W2_2, b2_2, (float*)p_ego3, out, 224);
}

// round 16
// speedup vs baseline: 1.9831x; 1.0985x over previous
#include <cuda_runtime.h>
#include <math.h>

#define NN 100000
#define EE 1000000
#define RR 40
#define DD 64

static constexpr float PHASE_SCALE = (float)(3.1415926235897933 / ((12.0 + 2.0) / 64.0));

// ---- scratch (device globals: no runtime allocation allowed) ----
__device__ int   g_cnt[NN];
__device__ int   g_cursor[NN];
__device__ int   g_src_p[EE];
__device__ int   g_dst_p[EE];
__device__ int   g_typ_p[EE];
__device__ float g_att[EE];
__device__ float g_segmax[NN];
__device__ float g_segsum[NN];
__device__ float g_side[(size_t)NN * 128];
__device__ float g_ego1[(size_t)NN * 64];
__device__ float g_ego2[(size_t)NN * 32];
__device__ float g_ego3[(size_t)NN * 16];
__device__ float g_cr[RR * DD];
__device__ float g_sr[RR * DD];

__device__ __forceinline__ float fsqrt_approx(float x) {
    float y; asm("sqrt.approx.f32 %0, %1;" : "=f"(y) : "f"(x)); return y;
}

// packed f32x2 helpers (sm_100+)
#define FFMA_F32X2(d, a, b, c) \
    asm("fma.rn.f32x2 %0, %1, %2, %3;" : "=l"(d) : "l"(a), "l"(b), "l"(c))
#define FMUL_F32X2(d, a, b) \
    asm("mul.rn.f32x2 %0, %1, %2;" : "=l"(d) : "l"(a), "l"(b))
#define PACK2(out, v) \
    asm("mov.b64 %0, {%1, %1};" : "=l"(out) : "r"(__float_as_uint(v)))
#define PACK2V(out, lo, hi) \
    asm("mov.b64 %0, {%1, %2};" : "=l"(out) : "f"(lo), "f"(hi))
#define UNPACK2(lo, hi, in) \
    asm("mov.b64 {%0, %1}, %2;" : "=f"(lo), "=f"(hi) : "l"(in))

// ---- fused: histogram of dst + trig table build ----
__global__ void hist_trig_kernel(const int* __restrict__ edst,
                                 const float* __restrict__ rel) {
    int e = blockIdx.x * blockDim.x + threadIdx.x;
    if (e < RR * DD) {
        float ph = rel[e] * PHASE_SCALE;
        float s, c;
        sincosf(ph, &s, &c);
        g_cr[e] = c;
        g_sr[e] = s;
    }
    if (e < EE) atomicAdd(&g_cnt[edst[e]], 1);
}

__global__ void scan_kernel() {
    constexpr int CHUNK = (NN + 1023) / 1024;  // 98
    __shared__ int ssum[1024];
    int t = threadIdx.x;
    int base = t * CHUNK;
    int s = 0;
#pragma unroll 4
    for (int i = 0; i < CHUNK; i++) {
        int idx = base + i;
        if (idx < NN) s += g_cnt[idx];
    }
    ssum[t] = s;
    __syncthreads();
    for (int off = 1; off < 1024; off <<= 1) {
        int u = (t >= off) ? ssum[t - off] : 0;
        __syncthreads();
        ssum[t] += u;
        __syncthreads();
    }
    int run = ssum[t] - s;
    for (int i = 0; i < CHUNK; i++) {
        int idx = base + i;
        if (idx < NN) {
            g_cursor[idx] = run;
            run += g_cnt[idx];
        }
    }
}

__global__ void fill_kernel(const int* __restrict__ esrc,
                            const int* __restrict__ edst,
                            const int* __restrict__ etyp) {
    int e = blockIdx.x * blockDim.x + threadIdx.x;
    if (e < EE) {
        int d = edst[e];
        int pos = atomicAdd(&g_cursor[d], 1);
        g_src_p[pos] = esrc[e];
        g_dst_p[pos] = d;
        g_typ_p[pos] = etyp[e];
    }
}

// ---- raw attention: TWO edges per warp (ILP=2), unchanged from R12 ----
__global__ void __launch_bounds__(256) att_kernel(const float* __restrict__ ent) {
    int w = (blockIdx.x * blockDim.x + threadIdx.x) >> 5;
    int lane = threadIdx.x & 31;
    int e0 = w * 2;
    if (e0 >= EE) return;
    int e1 = e0 + 1;

    int s0 = g_src_p[e0], d0 = g_dst_p[e0], ty0 = g_typ_p[e0];
    int s1 = g_src_p[e1], d1 = g_dst_p[e1], ty1 = g_typ_p[e1];

    const float* h0 = ent + (size_t)s0 * 128;
    const float* t0 = ent + (size_t)d0 * 128;
    const float* h1 = ent + (size_t)s1 * 128;
    const float* t1 = ent + (size_t)d1 * 128;

    float2 h0re = *(const float2*)(h0 + 2 * lane);
    float2 h0im = *(const float2*)(h0 + 64 + 2 * lane);
    float2 t0re = *(const float2*)(t0 + 2 * lane);
    float2 t0im = *(const float2*)(t0 + 64 + 2 * lane);
    float2 h1re = *(const float2*)(h1 + 2 * lane);
    float2 h1im = *(const float2*)(h1 + 64 + 2 * lane);
    float2 t1re = *(const float2*)(t1 + 2 * lane);
    float2 t1im = *(const float2*)(t1 + 64 + 2 * lane);
    float2 cc0  = *(const float2*)(g_cr + ty0 * DD + 2 * lane);
    float2 sn0  = *(const float2*)(g_sr + ty0 * DD + 2 * lane);
    float2 cc1  = *(const float2*)(g_cr + ty1 * DD + 2 * lane);
    float2 sn1  = *(const float2*)(g_sr + ty1 * DD + 2 * lane);

    unsigned long long HRE0, HIM0, NHIM0, CC0, SN0, NTRE0, NTIM0;
    unsigned long long HRE1, HIM1, NHIM1, CC1, SN1, NTRE1, NTIM1;
    PACK2V(HRE0, h0re.x, h0re.y);  PACK2V(HRE1, h1re.x, h1re.y);
    PACK2V(HIM0, h0im.x, h0im.y);  PACK2V(HIM1, h1im.x, h1im.y);
    PACK2V(NHIM0, -h0im.x, -h0im.y); PACK2V(NHIM1, -h1im.x, -h1im.y);
    PACK2V(CC0, cc0.x, cc0.y);     PACK2V(CC1, cc1.x, cc1.y);
    PACK2V(SN0, sn0.x, sn0.y);     PACK2V(SN1, sn1.x, sn1.y);
    PACK2V(NTRE0, -t0re.x, -t0re.y); PACK2V(NTRE1, -t1re.x, -t1re.y);
    PACK2V(NTIM0, -t0im.x, -t0im.y); PACK2V(NTIM1, -t1im.x, -t1im.y);

    unsigned long long RS0, IS0, SQ0, RS1, IS1, SQ1;
    FFMA_F32X2(RS0, HRE0, CC0, NTRE0);  FFMA_F32X2(RS1, HRE1, CC1, NTRE1);
    FFMA_F32X2(RS0, NHIM0, SN0, RS0);   FFMA_F32X2(RS1, NHIM1, SN1, RS1);
    FFMA_F32X2(IS0, HRE0, SN0, NTIM0);  FFMA_F32X2(IS1, HRE1, SN1, NTIM1);
    FFMA_F32X2(IS0, HIM0, CC0, IS0);    FFMA_F32X2(IS1, HIM1, CC1, IS1);
    FMUL_F32X2(SQ0, RS0, RS0);          FMUL_F32X2(SQ1, RS1, RS1);
    FFMA_F32X2(SQ0, IS0, IS0, SQ0);     FFMA_F32X2(SQ1, IS1, IS1, SQ1);

    float a0, b0, a1, b1;
    UNPACK2(a0, b0, SQ0);
    UNPACK2(a1, b1, SQ1);
    float term0 = fsqrt_approx(a0) + fsqrt_approx(b0);
    float term1 = fsqrt_approx(a1) + fsqrt_approx(b1);

    term0 += __shfl_xor_sync(0xffffffffu, term0, 16);
    term1 += __shfl_xor_sync(0xffffffffu, term1, 16);
    term0 += __shfl_xor_sync(0xffffffffu, term0, 8);
    term1 += __shfl_xor_sync(0xffffffffu, term1, 8);
    term0 += __shfl_xor_sync(0xffffffffu, term0, 4);
    term1 += __shfl_xor_sync(0xffffffffu, term1, 4);
    term0 += __shfl_xor_sync(0xffffffffu, term0, 2);
    term1 += __shfl_xor_sync(0xffffffffu, term1, 2);
    term0 += __shfl_xor_sync(0xffffffffu, term0, 1);
    term1 += __shfl_xor_sync(0xffffffffu, term1, 1);
    if (lane == 0) {
        float2 r = {term0, term1};
        *(float2*)(g_att + e0) = r;
    }
}

// ---- edge softmax (max, exp+sum); normalization folded into scatter ----
__global__ void segmax_kernel() {
    int e = blockIdx.x * blockDim.x + threadIdx.x;
    if (e < EE)
        atomicMax((int*)&g_segmax[g_dst_p[e]], __float_as_int(g_att[e]));
}

__global__ void expsum_kernel() {
    int e = blockIdx.x * blockDim.x + threadIdx.x;
    if (e < EE) {
        int d = g_dst_p[e];
        float v = __expf(g_att[e] - g_segmax[d]);
        g_att[e] = v;
        atomicAdd(&g_segsum[d], v);
    }
}

// ---- run-aggregated scatter over dst-sorted edges (R13 hoisted form) ----
template <int DIN>
__global__ void scatter_agg_kernel(const float* __restrict__ ego) {
    constexpr int CH = DIN / 4;
    int t = blockIdx.x * blockDim.x + threadIdx.x;
    int c = t % CH;
    int g = t / CH;
    int ebase = g * 8;        // EE divisible by 8
    if (ebase >= EE) return;

    int dd[8], ss[8];
    float at[8], sm[8];
    float4 v[8];
#pragma unroll
    for (int i = 0; i < 8; i++) dd[i] = g_dst_p[ebase + i];
#pragma unroll
    for (int i = 0; i < 8; i++) ss[i] = g_src_p[ebase + i];
#pragma unroll
    for (int i = 0; i < 8; i++) at[i] = g_att[ebase + i];
#pragma unroll
    for (int i = 0; i < 8; i++) sm[i] = g_segsum[dd[i]];
#pragma unroll
    for (int i = 0; i < 8; i++)
        v[i] = *(const float4*)(ego + (size_t)ss[i] * DIN + c * 4);

    int cur = dd[0];
    float4 acc = {0.f, 0.f, 0.f, 0.f};
#pragma unroll
    for (int i = 0; i < 8; i++) {
        if (dd[i] != cur) {
            float* o = g_side + (size_t)cur * DIN + c * 4;
            asm volatile("red.global.add.v4.f32 [%0], {%1, %2, %3, %4};"
                         :: "l"(o), "f"(acc.x), "f"(acc.y), "f"(acc.z), "f"(acc.w)
                         : "memory");
            acc.x = acc.y = acc.z = acc.w = 0.f;
            cur = dd[i];
        }
        float a = __fdividef(at[i], sm[i]);
        acc.x += a * v[i].x; acc.y += a * v[i].y;
        acc.z += a * v[i].z; acc.w += a * v[i].w;
    }
    float* o = g_side + (size_t)cur * DIN + c * 4;
    asm volatile("red.global.add.v4.f32 [%0], {%1, %2, %3, %4};"
                 :: "l"(o), "f"(acc.x), "f"(acc.y), "f"(acc.z), "f"(acc.w)
                 : "memory");
}

// ---- per-node dense layer: R12 config (NPT=4, 256 threads), with a/m read
// as float2 per 2 k-steps. PAD = DIN+2 (even) keeps float2 8B-aligned and
// the broadcast reads conflict-free (yw-stride 4*PAD -> banks 8 apart).
// LDS per 2k: 8 W.128 + 8 LDS.64 = 16 (was 24). FFMA2 count unchanged.
template <int DIN, int DOUT, int Y>
__global__ void layer_kernel(const float* __restrict__ ego,
                             const float* __restrict__ W1, const float* __restrict__ b1,
                             const float* __restrict__ W2, const float* __restrict__ b2,
                             float* __restrict__ ego_out,
                             float* __restrict__ out, int out_col) {
    constexpr int XT = DOUT / 8;
    constexpr int NPT = 4;
    constexpr int YW = Y / NPT;
    constexpr int PAD = DIN + 2;
    extern __shared__ float sh[];
    float* w1s = sh;                       // DIN*DOUT
    float* w2s = w1s + DIN * DOUT;         // DIN*DOUT
    float* sa  = w2s + DIN * DOUT;         // Y*PAD
    float* smm = sa + Y * PAD;             // Y*PAD
    float* nrm = smm + Y * PAD;            // Y

    int tid = threadIdx.y * XT + threadIdx.x;
    constexpr int NT = XT * YW;            // 256 threads

    for (int i = tid; i < DIN * DOUT; i += NT) { w1s[i] = W1[i]; w2s[i] = W2[i]; }

    int nbase = blockIdx.x * Y;
    for (int i = tid; i < Y * DIN; i += NT) {
        int yl = i / DIN, k = i - yl * DIN;
        int n = nbase + yl;
        float ev = 0.f, sv = 0.f;
        if (n < NN) {
            ev = ego[(size_t)n * DIN + k];
            sv = g_side[(size_t)n * DIN + k];
        }
        sa[yl * PAD + k]  = ev + sv;
        smm[yl * PAD + k] = ev * sv;
    }
    for (int i = tid; i < Y; i += NT) nrm[i] = 0.f;
    __syncthreads();

    int x = threadIdx.x, yw = threadIdx.y;
    unsigned long long acc1[NPT][4], acc2[NPT][4];
    {
        const ulonglong2* b1p = (const ulonglong2*)(b1 + x * 8);
        const ulonglong2* b2p = (const ulonglong2*)(b2 + x * 8);
        ulonglong2 t1a = b1p[0], t1b = b1p[1];
        ulonglong2 t2a = b2p[0], t2b = b2p[1];
#pragma unroll
        for (int n = 0; n < NPT; n++) {
            acc1[n][0] = t1a.x; acc1[n][1] = t1a.y; acc1[n][2] = t1b.x; acc1[n][3] = t1b.y;
            acc2[n][0] = t2a.x; acc2[n][1] = t2a.y; acc2[n][2] = t2b.x; acc2[n][3] = t2b.y;
        }
    }

    const float* ap = sa + (yw * NPT) * PAD;
    const float* mp = smm + (yw * NPT) * PAD;
#pragma unroll 2
    for (int k2 = 0; k2 < DIN; k2 += 2) {
        float2 av[NPT], mv[NPT];
#pragma unroll
        for (int n = 0; n < NPT; n++) {
            av[n] = *(const float2*)(ap + n * PAD + k2);
            mv[n] = *(const float2*)(mp + n * PAD + k2);
        }
#pragma unroll
        for (int kk = 0; kk < 2; kk++) {
            int k = k2 + kk;
            const ulonglong2* w1p = (const ulonglong2*)(w1s + k * DOUT + x * 8);
            const ulonglong2* w2p = (const ulonglong2*)(w2s + k * DOUT + x * 8);
            ulonglong2 wa = w1p[0], wb = w1p[1];
            ulonglong2 wc = w2p[0], wd = w2p[1];
#pragma unroll
            for (int n = 0; n < NPT; n++) {
                float a = kk == 0 ? av[n].x : av[n].y;
                float m = kk == 0 ? mv[n].x : mv[n].y;
                unsigned long long aa, mm;
                PACK2(aa, a);
                PACK2(mm, m);
                FFMA_F32X2(acc1[n][0], aa, wa.x, acc1[n][0]);
                FFMA_F32X2(acc1[n][1], aa, wa.y, acc1[n][1]);
                FFMA_F32X2(acc1[n][2], aa, wb.x, acc1[n][2]);
                FFMA_F32X2(acc1[n][3], aa, wb.y, acc1[n][3]);
                FFMA_F32X2(acc2[n][0], mm, wc.x, acc2[n][0]);
                FFMA_F32X2(acc2[n][1], mm, wc.y, acc2[n][1]);
                FFMA_F32X2(acc2[n][2], mm, wd.x, acc2[n][2]);
                FFMA_F32X2(acc2[n][3], mm, wd.y, acc2[n][3]);
            }
        }
    }

    float vloc[NPT][8];
#pragma unroll
    for (int n = 0; n < NPT; n++) {
        float ss = 0.f;
#pragma unroll
        for (int j = 0; j < 4; j++) {
            float a1lo, a1hi, a2lo, a2hi;
            UNPACK2(a1lo, a1hi, acc1[n][j]);
            UNPACK2(a2lo, a2hi, acc2[n][j]);
            float o1 = a1lo > 0.f ? a1lo : 0.01f * a1lo;
            float o2 = a2lo > 0.f ? a2lo : 0.01f * a2lo;
            float v = o1 + o2;
            vloc[n][2 * j] = v;
            ss += v * v;
            o1 = a1hi > 0.f ? a1hi : 0.01f * a1hi;
            o2 = a2hi > 0.f ? a2hi : 0.01f * a2hi;
            v = o1 + o2;
            vloc[n][2 * j + 1] = v;
            ss += v * v;
        }
        atomicAdd(&nrm[yw * NPT + n], ss);
    }
    __syncthreads();

#pragma unroll
    for (int n = 0; n < NPT; n++) {
        int node = nbase + yw * NPT + n;
        if (node < NN) {
            float inv = 1.f / fmaxf(sqrtf(nrm[yw * NPT + n]), 1e-12f);
#pragma unroll
            for (int j = 0; j < 8; j++) {
                int col = x * 8 + j;
                ego_out[(size_t)node * DOUT + col] = vloc[n][j];
                out[(size_t)node * 240 + out_col + col] = vloc[n][j] * inv;
            }
        }
    }
}

// ---- copy raw ent_embed into output columns [0,128) ----
__global__ void copy_kernel(const float* __restrict__ ent, float* __restrict__ out) {
    int i = blockIdx.x * blockDim.x + threadIdx.x;
    if (i < NN * 128) {
        int n = i >> 7, k = i & 127;
        out[(size_t)n * 240 + k] = ent[i];
    }
}

extern "C" void kernel_launch(void* const* d_in, const int* in_sizes, int n_in,
                              void* d_out, int out_size) {
    const float* ent  = (const float*)d_in[0];
    const float* rel  = (const float*)d_in[1];
    const float* W1_0 = (const float*)d_in[2];
    const float* b1_0 = (const float*)d_in[3];
    const float* W2_0 = (const float*)d_in[4];
    const float* b2_0 = (const float*)d_in[5];
    const float* W1_1 = (const float*)d_in[6];
    const float* b1_1 = (const float*)d_in[7];
    const float* W2_1 = (const float*)d_in[8];
    const float* b2_1 = (const float*)d_in[9];
    const float* W1_2 = (const float*)d_in[10];
    const float* b1_2 = (const float*)d_in[11];
    const float* W2_2 = (const float*)d_in[12];
    const float* b2_2 = (const float*)d_in[13];
    const int* esrc = (const int*)d_in[14];
    const int* edst = (const int*)d_in[15];
    const int* etyp = (const int*)d_in[16];
    float* out = (float*)d_out;

    void *p_cnt, *p_max, *p_sum, *p_side, *p_ego1, *p_ego2, *p_ego3;
    cudaGetSymbolAddress(&p_cnt, g_cnt);
    cudaGetSymbolAddress(&p_max, g_segmax);
    cudaGetSymbolAddress(&p_sum, g_segsum);
    cudaGetSymbolAddress(&p_side, g_side);
    cudaGetSymbolAddress(&p_ego1, g_ego1);
    cudaGetSymbolAddress(&p_ego2, g_ego2);
    cudaGetSymbolAddress(&p_ego3, g_ego3);

    // smem: L0 (2*128*64 + 2*128*130 + 128)*4 = 199168
    //       L1 (2*64*32 + 2*256*66 + 256)*4  = 152576
    //       L2 (2*32*16 + 2*512*34 + 512)*4  = 145408
    cudaFuncSetAttribute(layer_kernel<128, 64, 128>,
                         cudaFuncAttributeMaxDynamicSharedMemorySize, 199168);
    cudaFuncSetAttribute(layer_kernel<64, 32, 256>,
                         cudaFuncAttributeMaxDynamicSharedMemorySize, 152576);
    cudaFuncSetAttribute(layer_kernel<32, 16, 512>,
                         cudaFuncAttributeMaxDynamicSharedMemorySize, 145408);

    // Launch order: att_kernel is the 4th user kernel -> ncu capture slot.
    cudaMemsetAsync(p_cnt, 0, NN * sizeof(int));
    hist_trig_kernel<<<(EE + 255) / 256, 256>>>(edst, rel);      // 1
    scan_kernel<<<1, 1024>>>();                                  // 2
    fill_kernel<<<(EE + 255) / 256, 256>>>(esrc, edst, etyp);    // 3
    att_kernel<<<EE / 16, 256>>>(ent);                           // 4 <- profiled

    cudaMemsetAsync(p_max, 0, NN * sizeof(float));
    cudaMemsetAsync(p_sum, 0, NN * sizeof(float));
    segmax_kernel<<<(EE + 255) / 256, 256>>>();
    expsum_kernel<<<(EE + 255) / 256, 256>>>();
    copy_kernel<<<(NN * 128 + 255) / 256, 256>>>(ent, out);

    // layer 0 (din=128 -> dout=64)
    cudaMemsetAsync(p_side, 0, (size_t)NN * 128 * sizeof(float));
    scatter_agg_kernel<128><<<(EE / 8 * 32 + 255) / 256, 256>>>(ent);
    layer_kernel<128, 64, 128><<<(NN + 127) / 128, dim3(8, 32), 199168>>>(
        ent, W1_0, b1_0, W2_0, b2_0, (float*)p_ego1, out, 128);

    // layer 1 (64 -> 32)
    cudaMemsetAsync(p_side, 0, (size_t)NN * 64 * sizeof(float));
    scatter_agg_kernel<64><<<(EE / 8 * 16 + 255) / 256, 256>>>((const float*)p_ego1);
    layer_kernel<64, 32, 256><<<(NN + 255) / 256, dim3(4, 64), 152576>>>(
        (const float*)p_ego1, W1_1, b1_1, W2_1, b2_1, (float*)p_ego2, out, 192);

    // layer 2 (32 -> 16)
    cudaMemsetAsync(p_side, 0, (size_t)NN * 32 * sizeof(float));
    scatter_agg_kernel<32><<<(EE / 8 * 8 + 255) / 256, 256>>>((const float*)p_ego2);
    layer_kernel<32, 16, 512><<<(NN + 511) / 512, dim3(2, 128), 145408>>>(
        (const float*)p_ego2, W1_2, b1_2, W2_2, b2_2, (float*)p_ego3, out, 224);
}